// round 2
// baseline (speedup 1.0000x reference)
#include <cuda_runtime.h>
#include <cuda_bf16.h>
#include <math.h>

// ---------------- problem constants ----------------
#define BB 32
#define TT 512
#define EPROJS 512
#define DUNITS 1024
#define ODIM 10000
#define ATT_DIM 320
#define LL 128
#define LP1 129
#define NTOK (LP1*BB)          // 4128
#define SOS_EOS (ODIM-1)

// ---------------- device scratch ----------------
__device__ float g_preenc[BB*ATT_DIM*TT];       // [b][a][t]
__device__ float g_eys[LP1*BB*DUNITS];          // [l][b][d]
__device__ float g_zs[LP1*BB*DUNITS];           // [l][b][d] (z1 outputs)
__device__ float g_xcat[BB*1536];               // [b][ ey(1024) | att_c(512) ]
__device__ float g_z0[2][BB*DUNITS];
__device__ float g_c0[2][BB*DUNITS];
__device__ float g_z1[2][BB*DUNITS];
__device__ float g_c1[2][BB*DUNITS];
__device__ float g_logits[(long)NTOK*ODIM];     // 165 MB
__device__ float g_nll[NTOK];
__device__ float g_cor[NTOK];

__device__ __forceinline__ float sigf(float x) { return 1.0f / (1.0f + expf(-x)); }

// ---------------- init ----------------
__global__ void init_state() {
    int i = blockIdx.x * 256 + threadIdx.x;
    if (i < BB * DUNITS) {
        g_z0[0][i] = 0.f; g_c0[0][i] = 0.f;
        g_z1[0][i] = 0.f; g_c1[0][i] = 0.f;
    }
}

// ---------------- embedding gather ----------------
__global__ void embed_kernel(const float* __restrict__ embed_w, const int* __restrict__ ys_pad) {
    int idx = blockIdx.x * 256 + threadIdx.x;
    if (idx >= LP1 * BB * DUNITS) return;
    int d  = idx & (DUNITS - 1);
    int rb = idx >> 10;         // l*32+b
    int b  = rb & 31;
    int l  = rb >> 5;
    int tok = (l == 0) ? SOS_EOS : ys_pad[b * LL + (l - 1)];
    g_eys[idx] = embed_w[(long)tok * DUNITS + d];
}

// ---------------- generic tiled SGEMM: C[M,N] = A[M,K] * B[N,K]^T (+bias, act) ----------------
// csel: 0 -> C = g_preenc (batched via blockIdx.z), 1 -> C = g_logits
// Aopt: if null, A = g_zs
#define SG_BM 64
#define SG_BN 64
#define SG_BK 16
__global__ __launch_bounds__(256) void sgemm_tn(
    const float* __restrict__ Aopt, const float* __restrict__ Bm, int csel,
    int M, int N, int K, long sA, long sB, long sC,
    const float* __restrict__ biasM, const float* __restrict__ biasN, int act)
{
    const float* A = Aopt ? Aopt : g_zs;
    float* C = (csel == 0) ? g_preenc : g_logits;
    A += (long)blockIdx.z * sA;
    const float* B = Bm + (long)blockIdx.z * sB;
    C += (long)blockIdx.z * sC;

    int m0 = blockIdx.y * SG_BM, n0 = blockIdx.x * SG_BN;
    __shared__ float As[SG_BK][SG_BM + 4];
    __shared__ float Bs[SG_BK][SG_BN + 4];
    int tid = threadIdx.x;
    int ty = tid >> 4, tx = tid & 15;
    int lr = tid >> 2;            // 0..63
    int lk = (tid & 3) * 4;       // 0,4,8,12
    float acc[4][4];
#pragma unroll
    for (int i = 0; i < 4; i++)
#pragma unroll
        for (int j = 0; j < 4; j++) acc[i][j] = 0.f;

    for (int k0 = 0; k0 < K; k0 += SG_BK) {
        float4 av = make_float4(0.f, 0.f, 0.f, 0.f);
        int gm = m0 + lr;
        if (gm < M) av = *(const float4*)&A[(long)gm * K + k0 + lk];
        float4 bv = make_float4(0.f, 0.f, 0.f, 0.f);
        int gn = n0 + lr;
        if (gn < N) bv = *(const float4*)&B[(long)gn * K + k0 + lk];
        __syncthreads();
        As[lk + 0][lr] = av.x; As[lk + 1][lr] = av.y; As[lk + 2][lr] = av.z; As[lk + 3][lr] = av.w;
        Bs[lk + 0][lr] = bv.x; Bs[lk + 1][lr] = bv.y; Bs[lk + 2][lr] = bv.z; Bs[lk + 3][lr] = bv.w;
        __syncthreads();
#pragma unroll
        for (int kk = 0; kk < SG_BK; kk++) {
            float4 a = *(const float4*)&As[kk][ty * 4];
            float4 b = *(const float4*)&Bs[kk][tx * 4];
            float aa[4] = {a.x, a.y, a.z, a.w};
            float bb[4] = {b.x, b.y, b.z, b.w};
#pragma unroll
            for (int i = 0; i < 4; i++)
#pragma unroll
                for (int j = 0; j < 4; j++) acc[i][j] += aa[i] * bb[j];
        }
    }
#pragma unroll
    for (int i = 0; i < 4; i++) {
        int row = m0 + ty * 4 + i;
        if (row >= M) continue;
        float bm = biasM ? biasM[row] : 0.f;
#pragma unroll
        for (int j = 0; j < 4; j++) {
            int col = n0 + tx * 4 + j;
            if (col >= N) continue;
            float v = acc[i][j] + bm + (biasN ? biasN[col] : 0.f);
            if (act == 1) v = tanhf(v);
            C[(long)row * N + col] = v;
        }
    }
}

// ---------------- per-step attention (one block per batch row) ----------------
__global__ __launch_bounds__(256) void attn_kernel(
    const float* __restrict__ hs, const int* __restrict__ hlens,
    const float* __restrict__ Wdec, int l, int cur)
{
    int b = blockIdx.x;
    int tid = threadIdx.x;
    int lane = tid & 31, wid = tid >> 5;
    __shared__ float z0sh[DUNITS];
    __shared__ float decsh[ATT_DIM];
    __shared__ float esh[TT];
    __shared__ float red[8];

    const float* z0 = g_z0[cur] + b * DUNITS;
    for (int i = tid; i < DUNITS; i += 256) z0sh[i] = z0[i];
    __syncthreads();

    // dec = tanh(z0 @ Wdec^T)
    for (int a = tid; a < ATT_DIM; a += 256) {
        const float4* wr = (const float4*)(Wdec + (long)a * DUNITS);
        const float4* zr = (const float4*)z0sh;
        float s = 0.f;
#pragma unroll 4
        for (int q = 0; q < DUNITS / 4; q++) {
            float4 w = wr[q]; float4 z = zr[q];
            s += w.x * z.x + w.y * z.y + w.z * z.z + w.w * z.w;
        }
        decsh[a] = tanhf(s);
    }
    __syncthreads();

    // e[t] = pre_enc[b,t,:] . dec ; masked scale
    int tl = hlens[b];
    float ev[2];
#pragma unroll
    for (int it = 0; it < 2; it++) {
        int t = tid + it * 256;
        const float* pe = g_preenc + ((long)b * ATT_DIM) * TT + t;
        float s = 0.f;
#pragma unroll 4
        for (int a = 0; a < ATT_DIM; a++) s += pe[a * TT] * decsh[a];
        ev[it] = (t < tl) ? 2.0f * s : -1e10f;
    }
    // block max
    float m = fmaxf(ev[0], ev[1]);
#pragma unroll
    for (int o = 16; o; o >>= 1) m = fmaxf(m, __shfl_xor_sync(0xffffffffu, m, o));
    if (lane == 0) red[wid] = m;
    __syncthreads();
    m = red[0];
#pragma unroll
    for (int w = 1; w < 8; w++) m = fmaxf(m, red[w]);
    float e0 = expf(ev[0] - m), e1 = expf(ev[1] - m);
    float s = e0 + e1;
#pragma unroll
    for (int o = 16; o; o >>= 1) s += __shfl_xor_sync(0xffffffffu, s, o);
    __syncthreads();
    if (lane == 0) red[wid] = s;
    __syncthreads();
    s = 0.f;
#pragma unroll
    for (int w = 0; w < 8; w++) s += red[w];
    float inv = 1.0f / s;
    esh[tid] = e0 * inv;
    esh[tid + 256] = e1 * inv;
    __syncthreads();

    // att_c[d] = sum_t w[t]*hs[b,t,d] -> xcat[b][1024+d]
    for (int d = tid; d < EPROJS; d += 256) {
        const float* hp = hs + ((long)b * TT) * EPROJS + d;
        float acc = 0.f;
#pragma unroll 4
        for (int t = 0; t < TT; t++) acc += esh[t] * hp[t * EPROJS];
        g_xcat[b * 1536 + 1024 + d] = acc;
    }
    // copy embedding slice -> xcat[b][0:1024]
    for (int d = tid; d < DUNITS; d += 256)
        g_xcat[b * 1536 + d] = g_eys[((long)l * BB + b) * DUNITS + d];
}

// ---------------- LSTM cell: gates GEMM + fused activation ----------------
// 128 blocks (8 units each), 128 threads; block computes 32 rows x 32 gate-cols.
__global__ __launch_bounds__(128) void lstm_kernel(
    const float* __restrict__ Wih, const float* __restrict__ Whh,
    const float* __restrict__ bih, const float* __restrict__ bhh,
    int layer, int cur, int l)
{
    int nxt = cur ^ 1;
    const float* x; int ldx, Kx;
    const float* h; const float* cin; float* zout; float* cout; float* zsrow = nullptr;
    if (layer == 0) {
        x = g_xcat; ldx = 1536; Kx = 1536;
        h = g_z0[cur]; cin = g_c0[cur]; zout = g_z0[nxt]; cout = g_c0[nxt];
    } else {
        x = g_z0[nxt]; ldx = 1024; Kx = 1024;
        h = g_z1[cur]; cin = g_c1[cur]; zout = g_z1[nxt]; cout = g_c1[nxt];
        zsrow = g_zs + (long)l * BB * DUNITS;
    }

    __shared__ float xs[32 * 16];
    __shared__ float ws[32 * 16];
    __shared__ float gsh[32][32];
    int tid = threadIdx.x;
    int u0 = blockIdx.x * 8;
    int rg = tid >> 3;
    int cb = (tid & 7) * 4;
    int lr = tid >> 2;           // 0..31 (row for x-tile, col for w-tile)
    int lq = (tid & 3) * 4;
    int nw = ((lr >> 3) << 10) + u0 + (lr & 7);   // W row for this loader thread

    float acc[2][4];
#pragma unroll
    for (int i = 0; i < 2; i++)
#pragma unroll
        for (int j = 0; j < 4; j++) acc[i][j] = 0.f;

    int ntx = Kx >> 4;
    int ntot = ntx + 64;
    for (int t = 0; t < ntot; t++) {
        const float* src; int srcld; const float* W; int wld; int k0;
        if (t < ntx) { src = x;  srcld = ldx;  W = Wih; wld = Kx;   k0 = t * 16; }
        else         { src = h;  srcld = 1024; W = Whh; wld = 1024; k0 = (t - ntx) * 16; }
        float4 xv = *(const float4*)&src[lr * srcld + k0 + lq];
        float4 wv = *(const float4*)&W[(long)nw * wld + k0 + lq];
        __syncthreads();
        *(float4*)&xs[lr * 16 + lq] = xv;
        *(float4*)&ws[lr * 16 + lq] = wv;
        __syncthreads();
        const float4* xs4 = (const float4*)xs;
        const float4* ws4 = (const float4*)ws;
#pragma unroll
        for (int q = 0; q < 4; q++) {
            float4 xa = xs4[rg * 4 + q];
            float4 xb = xs4[(rg + 16) * 4 + q];
#pragma unroll
            for (int j = 0; j < 4; j++) {
                float4 w = ws4[(cb + j) * 4 + q];
                acc[0][j] += xa.x * w.x + xa.y * w.y + xa.z * w.z + xa.w * w.w;
                acc[1][j] += xb.x * w.x + xb.y * w.y + xb.z * w.z + xb.w * w.w;
            }
        }
    }
    __syncthreads();
#pragma unroll
    for (int j = 0; j < 4; j++) {
        gsh[rg][cb + j] = acc[0][j];
        gsh[rg + 16][cb + j] = acc[1][j];
    }
    __syncthreads();
    for (int o = tid; o < 256; o += 128) {
        int r = o >> 3; int j = o & 7; int u = u0 + j;
        float ig = gsh[r][j]      + bih[u]        + bhh[u];
        float fg = gsh[r][8 + j]  + bih[1024 + u] + bhh[1024 + u];
        float gg = gsh[r][16 + j] + bih[2048 + u] + bhh[2048 + u];
        float og = gsh[r][24 + j] + bih[3072 + u] + bhh[3072 + u];
        float c2 = sigf(fg) * cin[r * 1024 + u] + sigf(ig) * tanhf(gg);
        float h2 = sigf(og) * tanhf(c2);
        cout[r * 1024 + u] = c2;
        zout[r * 1024 + u] = h2;
        if (zsrow) zsrow[r * 1024 + u] = h2;
    }
}

// ---------------- per-row softmax reduce over logits ----------------
__global__ __launch_bounds__(256) void rowred_kernel(const int* __restrict__ ys_pad) {
    int r = blockIdx.x;               // 0..4127, r = l*32+b
    int l = r >> 5; int b = r & 31;
    int tok = (l < LL) ? ys_pad[b * LL + l] : SOS_EOS;
    const float* row = g_logits + (long)r * ODIM;
    int tid = threadIdx.x;
    __shared__ float rv[256];
    __shared__ int ri[256];

    float m = -1e30f; int mi = 0;
    for (int c = tid; c < ODIM; c += 256) {
        float v = row[c];
        if (v > m) { m = v; mi = c; }
    }
    rv[tid] = m; ri[tid] = mi;
    __syncthreads();
    for (int s = 128; s; s >>= 1) {
        if (tid < s) {
            float v2 = rv[tid + s]; int i2 = ri[tid + s];
            if (v2 > rv[tid] || (v2 == rv[tid] && i2 < ri[tid])) { rv[tid] = v2; ri[tid] = i2; }
        }
        __syncthreads();
    }
    float gm = rv[0]; int gmi = ri[0];
    __syncthreads();

    float s = 0.f;
    for (int c = tid; c < ODIM; c += 256) s += expf(row[c] - gm);
    rv[tid] = s;
    __syncthreads();
    for (int st = 128; st; st >>= 1) {
        if (tid < st) rv[tid] += rv[tid + st];
        __syncthreads();
    }
    if (tid == 0) {
        g_nll[r] = gm + logf(rv[0]) - row[tok];
        g_cor[r] = (gmi == tok) ? 1.f : 0.f;
    }
}

// ---------------- final scalars ----------------
__global__ __launch_bounds__(256) void final_kernel(float* __restrict__ out) {
    __shared__ float sn[256];
    __shared__ float sc[256];
    int tid = threadIdx.x;
    float ns = 0.f, cs = 0.f;
    for (int r = tid; r < NTOK; r += 256) { ns += g_nll[r]; cs += g_cor[r]; }
    sn[tid] = ns; sc[tid] = cs;
    __syncthreads();
    for (int s = 128; s; s >>= 1) {
        if (tid < s) { sn[tid] += sn[tid + s]; sc[tid] += sc[tid + s]; }
        __syncthreads();
    }
    if (tid == 0) {
        float loss = sn[0] / (float)NTOK * (float)LL;
        out[0] = loss;
        out[1] = sc[0] / (float)NTOK;
        out[2] = expf(loss / (float)BB);
    }
}

// ---------------- launch ----------------
extern "C" void kernel_launch(void* const* d_in, const int* in_sizes, int n_in,
                              void* d_out, int out_size)
{
    const float* hs     = (const float*)d_in[0];
    const int*   hlens  = (const int*)d_in[1];
    const int*   ys     = (const int*)d_in[2];
    const float* embedw = (const float*)d_in[3];
    const float* Wenc   = (const float*)d_in[4];
    const float* benc   = (const float*)d_in[5];
    const float* Wdec   = (const float*)d_in[6];
    const float* Wih0   = (const float*)d_in[7];
    const float* Whh0   = (const float*)d_in[8];
    const float* bih0   = (const float*)d_in[9];
    const float* bhh0   = (const float*)d_in[10];
    const float* Wih1   = (const float*)d_in[11];
    const float* Whh1   = (const float*)d_in[12];
    const float* bih1   = (const float*)d_in[13];
    const float* bhh1   = (const float*)d_in[14];
    const float* Wout   = (const float*)d_in[15];
    const float* bout   = (const float*)d_in[16];
    float* out = (float*)d_out;

    init_state<<<128, 256>>>();
    embed_kernel<<<(LP1 * BB * DUNITS + 255) / 256, 256>>>(embedw, ys);

    {   // pre_enc[b][a][t] = tanh(Wenc @ hs_b^T + benc)
        dim3 g(TT / SG_BN, ATT_DIM / SG_BM, BB);
        sgemm_tn<<<g, 256>>>(Wenc, hs, 0, ATT_DIM, TT, EPROJS,
                             0L, (long)TT * EPROJS, (long)ATT_DIM * TT,
                             benc, nullptr, 1);
    }

    int cur = 0;
    for (int l = 0; l < LP1; l++) {
        attn_kernel<<<BB, 256>>>(hs, hlens, Wdec, l, cur);
        lstm_kernel<<<128, 128>>>(Wih0, Whh0, bih0, bhh0, 0, cur, l);
        lstm_kernel<<<128, 128>>>(Wih1, Whh1, bih1, bhh1, 1, cur, l);
        cur ^= 1;
    }

    {   // logits = zs @ Wout^T + bout
        dim3 g((ODIM + SG_BN - 1) / SG_BN, (NTOK + SG_BM - 1) / SG_BM, 1);
        sgemm_tn<<<g, 256>>>(nullptr, Wout, 1, NTOK, ODIM, DUNITS,
                             0L, 0L, 0L, nullptr, bout, 0);
    }
    rowred_kernel<<<NTOK, 256>>>(ys);
    final_kernel<<<1, 256>>>(out);
    (void)in_sizes; (void)n_in; (void)out_size;
}

// round 7
// speedup vs baseline: 3.1163x; 3.1163x over previous
#include <cuda_runtime.h>
#include <cuda_bf16.h>
#include <math.h>

#define BB 32
#define TT 512
#define EPROJS 512
#define DUNITS 1024
#define ODIM 10000
#define ATT_DIM 320
#define LL 128
#define LP1 129
#define NTOK (LP1*BB)
#define SOS_EOS (ODIM-1)

__device__ __align__(16) float g_preenc[BB*TT*ATT_DIM];   // [b][t][a]
__device__ __align__(16) float g_eys[LP1*BB*DUNITS];
__device__ __align__(16) float g_zs[LP1*BB*DUNITS];
__device__ __align__(16) float g_xcat[BB*1536];
__device__ __align__(16) float g_z0[2][BB*DUNITS];
__device__ __align__(16) float g_c0[2][BB*DUNITS];
__device__ __align__(16) float g_z1[2][BB*DUNITS];
__device__ __align__(16) float g_c1[2][BB*DUNITS];
__device__ __align__(16) float g_dec[BB*ATT_DIM];
__device__ __align__(16) float g_e[BB*TT];
__device__ __align__(16) float g_logits[(long)NTOK*ODIM];
__device__ float g_nll[NTOK];
__device__ float g_cor[NTOK];

__device__ __forceinline__ float sigf(float x) { return 1.0f / (1.0f + expf(-x)); }

__global__ void init_state() {
    int i = blockIdx.x * 256 + threadIdx.x;
    if (i < BB * DUNITS) {
        g_z0[0][i] = 0.f; g_c0[0][i] = 0.f;
        g_z1[0][i] = 0.f; g_c1[0][i] = 0.f;
    }
}

__global__ void embed_kernel(const float* __restrict__ embed_w, const int* __restrict__ ys_pad) {
    int idx = blockIdx.x * 256 + threadIdx.x;
    if (idx >= LP1 * BB * DUNITS) return;
    int d  = idx & (DUNITS - 1);
    int rb = idx >> 10;
    int b  = rb & 31;
    int l  = rb >> 5;
    int tok = (l == 0) ? SOS_EOS : ys_pad[b * LL + (l - 1)];
    g_eys[idx] = embed_w[(long)tok * DUNITS + d];
}

// ---------------- tiled SGEMM: C[M,N] = A[M,K] * B[N,K]^T (+biasN, act) ----------------
#define SG_BM 64
#define SG_BN 64
#define SG_BK 16
__global__ __launch_bounds__(256) void sgemm_tn(
    const float* __restrict__ Aopt, const float* __restrict__ Bm, int csel,
    int M, int N, int K, long sA, long sC,
    const float* __restrict__ biasN, int act)
{
    const float* A = (Aopt ? Aopt : g_zs) + (long)blockIdx.z * sA;
    const float* B = Bm;
    float* C = ((csel == 0) ? g_preenc : g_logits) + (long)blockIdx.z * sC;

    int m0 = blockIdx.y * SG_BM, n0 = blockIdx.x * SG_BN;
    __shared__ float As[SG_BK][SG_BM + 4];
    __shared__ float Bs[SG_BK][SG_BN + 4];
    int tid = threadIdx.x;
    int ty = tid >> 4, tx = tid & 15;
    int lr = tid >> 2;
    int lk = (tid & 3) * 4;
    float acc[4][4];
#pragma unroll
    for (int i = 0; i < 4; i++)
#pragma unroll
        for (int j = 0; j < 4; j++) acc[i][j] = 0.f;

    for (int k0 = 0; k0 < K; k0 += SG_BK) {
        float4 av = make_float4(0.f,0.f,0.f,0.f);
        int gm = m0 + lr;
        if (gm < M) av = *(const float4*)&A[(long)gm * K + k0 + lk];
        float4 bv = make_float4(0.f,0.f,0.f,0.f);
        int gn = n0 + lr;
        if (gn < N) bv = *(const float4*)&B[(long)gn * K + k0 + lk];
        __syncthreads();
        As[lk+0][lr]=av.x; As[lk+1][lr]=av.y; As[lk+2][lr]=av.z; As[lk+3][lr]=av.w;
        Bs[lk+0][lr]=bv.x; Bs[lk+1][lr]=bv.y; Bs[lk+2][lr]=bv.z; Bs[lk+3][lr]=bv.w;
        __syncthreads();
#pragma unroll
        for (int kk = 0; kk < SG_BK; kk++) {
            float4 a = *(const float4*)&As[kk][ty*4];
            float4 b = *(const float4*)&Bs[kk][tx*4];
            float aa[4] = {a.x,a.y,a.z,a.w};
            float bb[4] = {b.x,b.y,b.z,b.w};
#pragma unroll
            for (int i = 0; i < 4; i++)
#pragma unroll
                for (int j = 0; j < 4; j++) acc[i][j] += aa[i]*bb[j];
        }
    }
#pragma unroll
    for (int i = 0; i < 4; i++) {
        int row = m0 + ty*4 + i;
        if (row >= M) continue;
#pragma unroll
        for (int j = 0; j < 4; j++) {
            int col = n0 + tx*4 + j;
            if (col >= N) continue;
            float v = acc[i][j] + (biasN ? biasN[col] : 0.f);
            if (act == 1) v = tanhf(v);
            C[(long)row * N + col] = v;
        }
    }
}

// ---------------- dec = tanh(z0 @ Wdec^T), grid 128 = 32b x 4 chunks of 80 ----------------
__global__ __launch_bounds__(256) void dec_kernel(const float* __restrict__ Wdec, int cur) {
    int b = blockIdx.x >> 2, q = blockIdx.x & 3;
    __shared__ float z0sh[DUNITS];
    const float* z0 = g_z0[cur] + b * DUNITS;
    for (int i = threadIdx.x; i < DUNITS; i += 256) z0sh[i] = z0[i];
    __syncthreads();
    int w = threadIdx.x >> 5, lane = threadIdx.x & 31;
    const float4* zr = (const float4*)z0sh;
#pragma unroll
    for (int i = 0; i < 10; i++) {
        int a = q * 80 + w * 10 + i;
        const float4* wr = (const float4*)(Wdec + (long)a * DUNITS);
        float s = 0.f;
#pragma unroll
        for (int j = 0; j < 8; j++) {
            float4 wv = wr[lane + 32*j];
            float4 zv = zr[lane + 32*j];
            s += wv.x*zv.x + wv.y*zv.y + wv.z*zv.z + wv.w*zv.w;
        }
#pragma unroll
        for (int o = 16; o; o >>= 1) s += __shfl_xor_sync(0xffffffffu, s, o);
        if (lane == 0) g_dec[b * ATT_DIM + a] = tanhf(s);
    }
}

// ---------------- e[b][t] = 2*pre_enc[b][t][:].dec[b] (masked), grid 128 = 32b x 4 ----------------
__global__ __launch_bounds__(256) void escore_kernel(const int* __restrict__ hlens) {
    int b = blockIdx.x >> 2, tq = blockIdx.x & 3;
    __shared__ float decsh[ATT_DIM];
    for (int i = threadIdx.x; i < ATT_DIM; i += 256) decsh[i] = g_dec[b * ATT_DIM + i];
    __syncthreads();
    int tl = hlens[b];
    int w = threadIdx.x >> 5, lane = threadIdx.x & 31;
#pragma unroll
    for (int i = 0; i < 16; i++) {
        int t = tq * 128 + w * 16 + i;
        const float* pe = g_preenc + ((long)(b * TT + t)) * ATT_DIM;
        float s = 0.f;
#pragma unroll
        for (int j = 0; j < 10; j++) s += pe[lane + 32*j] * decsh[lane + 32*j];
#pragma unroll
        for (int o = 16; o; o >>= 1) s += __shfl_xor_sync(0xffffffffu, s, o);
        if (lane == 0) g_e[b * TT + t] = (t < tl) ? 2.0f * s : -1e10f;
    }
}

// ---------------- softmax + context + xcat assembly, grid 128 = 32b x 4 d-quarters ----------------
__global__ __launch_bounds__(256) void ctx_kernel(const float* __restrict__ hs, int l) {
    int b = blockIdx.x >> 2, dq = blockIdx.x & 3;
    int tid = threadIdx.x;
    int lane = tid & 31, wid = tid >> 5;
    __shared__ float wsh[TT];
    __shared__ float redm[8];
    __shared__ float reds[8];
    __shared__ float cred[128];

    float e0 = g_e[b * TT + tid];
    float e1 = g_e[b * TT + 256 + tid];
    float m = fmaxf(e0, e1);
#pragma unroll
    for (int o = 16; o; o >>= 1) m = fmaxf(m, __shfl_xor_sync(0xffffffffu, m, o));
    if (lane == 0) redm[wid] = m;
    __syncthreads();
    m = redm[0];
#pragma unroll
    for (int w = 1; w < 8; w++) m = fmaxf(m, redm[w]);
    float x0 = expf(e0 - m), x1 = expf(e1 - m);
    float s = x0 + x1;
#pragma unroll
    for (int o = 16; o; o >>= 1) s += __shfl_xor_sync(0xffffffffu, s, o);
    if (lane == 0) reds[wid] = s;
    __syncthreads();
    s = 0.f;
#pragma unroll
    for (int w = 0; w < 8; w++) s += reds[w];
    float inv = 1.0f / s;
    wsh[tid] = x0 * inv;
    wsh[tid + 256] = x1 * inv;
    __syncthreads();

    // ey copy: 4 blocks x 256 cover 1024
    int d2 = dq * 256 + tid;
    g_xcat[b * 1536 + d2] = g_eys[((long)l * BB + b) * DUNITS + d2];

    // context: this block's 128 d-cols; t split into 2 halves of 256
    int dd = dq * 128 + (tid & 127);
    int hh = tid >> 7;
    const float* hp = hs + ((long)(b * TT) + hh * 256) * EPROJS + dd;
    const float* wp = wsh + hh * 256;
    float acc = 0.f;
#pragma unroll 8
    for (int t = 0; t < 256; t++) acc += wp[t] * hp[(long)t * EPROJS];
    if (hh) cred[tid & 127] = acc;
    __syncthreads();
    if (!hh) g_xcat[b * 1536 + 1024 + dd] = acc + cred[tid & 127];
}

// ---------------- LSTM: 128 blocks x 256 thr; block = 32 rows x 32 gate-cols (8 units) ----------------
__global__ __launch_bounds__(256) void lstm_kernel(
    const float* __restrict__ Wih, const float* __restrict__ Whh,
    const float* __restrict__ bih, const float* __restrict__ bhh,
    int layer, int cur, int l)
{
    int nxt = cur ^ 1;
    const float* x; int ldx, nx;
    const float* h; const float* cin; float* zout; float* cout; float* zsrow = nullptr;
    if (layer == 0) {
        x = g_xcat; ldx = 1536; nx = 48;
        h = g_z0[cur]; cin = g_c0[cur]; zout = g_z0[nxt]; cout = g_c0[nxt];
    } else {
        x = g_z0[nxt]; ldx = 1024; nx = 32;
        h = g_z1[cur]; cin = g_c1[cur]; zout = g_z1[nxt]; cout = g_c1[nxt];
        zsrow = g_zs + (long)l * BB * DUNITS;
    }
    __shared__ float xs[32][32];
    __shared__ float ws[32][36];
    __shared__ float gsh[32][32];
    int tid = threadIdx.x;
    int u0 = blockIdx.x * 8;
    int r  = tid >> 3;            // compute row / load row / load col
    int cb = (tid & 7) * 4;       // compute col base
    int lq = (tid & 7) * 4;       // k-sub for loads
    int wrow = ((r >> 3) << 10) + u0 + (r & 7);   // W row for tile-col r
    float acc[4] = {0.f, 0.f, 0.f, 0.f};

    int ntot = nx + 32;
    float4 xv = *(const float4*)&x[r * ldx + lq];
    float4 wv = *(const float4*)&Wih[(long)wrow * ldx + lq];

    for (int t = 0; t < ntot; t++) {
        __syncthreads();
        *(float4*)&xs[r][lq] = xv;
        ws[lq+0][r] = wv.x; ws[lq+1][r] = wv.y; ws[lq+2][r] = wv.z; ws[lq+3][r] = wv.w;
        __syncthreads();
        int tn = t + 1;
        if (tn < ntot) {
            const float* src; int sld; const float* W; int wld; int k0;
            if (tn < nx) { src = x; sld = ldx;  W = Wih; wld = ldx;  k0 = tn * 32; }
            else         { src = h; sld = 1024; W = Whh; wld = 1024; k0 = (tn - nx) * 32; }
            xv = *(const float4*)&src[r * sld + k0 + lq];
            wv = *(const float4*)&W[(long)wrow * wld + k0 + lq];
        }
#pragma unroll
        for (int k = 0; k < 32; k++) {
            float xx = xs[r][k];
            float4 w4 = *(const float4*)&ws[k][cb];
            acc[0] += xx * w4.x; acc[1] += xx * w4.y;
            acc[2] += xx * w4.z; acc[3] += xx * w4.w;
        }
    }
    __syncthreads();
    gsh[r][cb+0] = acc[0]; gsh[r][cb+1] = acc[1];
    gsh[r][cb+2] = acc[2]; gsh[r][cb+3] = acc[3];
    __syncthreads();
    {
        int r2 = tid >> 3, j = tid & 7, u = u0 + j;
        float ig = gsh[r2][j]      + bih[u]        + bhh[u];
        float fg = gsh[r2][8 + j]  + bih[1024 + u] + bhh[1024 + u];
        float gg = gsh[r2][16 + j] + bih[2048 + u] + bhh[2048 + u];
        float og = gsh[r2][24 + j] + bih[3072 + u] + bhh[3072 + u];
        float c2 = sigf(fg) * cin[r2 * 1024 + u] + sigf(ig) * tanhf(gg);
        float h2 = sigf(og) * tanhf(c2);
        cout[r2 * 1024 + u] = c2;
        zout[r2 * 1024 + u] = h2;
        if (zsrow) zsrow[r2 * 1024 + u] = h2;
    }
}

// ---------------- per-row softmax reduce over logits ----------------
__global__ __launch_bounds__(256) void rowred_kernel(const int* __restrict__ ys_pad) {
    int rr = blockIdx.x;
    int l = rr >> 5; int b = rr & 31;
    int tok = (l < LL) ? ys_pad[b * LL + l] : SOS_EOS;
    const float* row = g_logits + (long)rr * ODIM;
    int tid = threadIdx.x;
    __shared__ float rv[256];
    __shared__ int ri[256];

    float m = -1e30f; int mi = 0;
    for (int c = tid; c < ODIM; c += 256) {
        float v = row[c];
        if (v > m) { m = v; mi = c; }
    }
    rv[tid] = m; ri[tid] = mi;
    __syncthreads();
    for (int s = 128; s; s >>= 1) {
        if (tid < s) {
            float v2 = rv[tid+s]; int i2 = ri[tid+s];
            if (v2 > rv[tid] || (v2 == rv[tid] && i2 < ri[tid])) { rv[tid] = v2; ri[tid] = i2; }
        }
        __syncthreads();
    }
    float gm = rv[0]; int gmi = ri[0];
    __syncthreads();

    float s = 0.f;
    for (int c = tid; c < ODIM; c += 256) s += expf(row[c] - gm);
    rv[tid] = s;
    __syncthreads();
    for (int st = 128; st; st >>= 1) {
        if (tid < st) rv[tid] += rv[tid+st];
        __syncthreads();
    }
    if (tid == 0) {
        g_nll[rr] = gm + logf(rv[0]) - row[tok];
        g_cor[rr] = (gmi == tok) ? 1.f : 0.f;
    }
}

__global__ __launch_bounds__(256) void final_kernel(float* __restrict__ out) {
    __shared__ float sn[256];
    __shared__ float sc[256];
    int tid = threadIdx.x;
    float ns = 0.f, cs = 0.f;
    for (int r = tid; r < NTOK; r += 256) { ns += g_nll[r]; cs += g_cor[r]; }
    sn[tid] = ns; sc[tid] = cs;
    __syncthreads();
    for (int s = 128; s; s >>= 1) {
        if (tid < s) { sn[tid] += sn[tid+s]; sc[tid] += sc[tid+s]; }
        __syncthreads();
    }
    if (tid == 0) {
        float loss = sn[0] / (float)NTOK * (float)LL;
        out[0] = loss;
        out[1] = sc[0] / (float)NTOK;
        out[2] = expf(loss / (float)BB);
    }
}

extern "C" void kernel_launch(void* const* d_in, const int* in_sizes, int n_in,
                              void* d_out, int out_size)
{
    const float* hs     = (const float*)d_in[0];
    const int*   hlens  = (const int*)d_in[1];
    const int*   ys     = (const int*)d_in[2];
    const float* embedw = (const float*)d_in[3];
    const float* Wenc   = (const float*)d_in[4];
    const float* benc   = (const float*)d_in[5];
    const float* Wdec   = (const float*)d_in[6];
    const float* Wih0   = (const float*)d_in[7];
    const float* Whh0   = (const float*)d_in[8];
    const float* bih0   = (const float*)d_in[9];
    const float* bhh0   = (const float*)d_in[10];
    const float* Wih1   = (const float*)d_in[11];
    const float* Whh1   = (const float*)d_in[12];
    const float* bih1   = (const float*)d_in[13];
    const float* bhh1   = (const float*)d_in[14];
    const float* Wout   = (const float*)d_in[15];
    const float* bout   = (const float*)d_in[16];
    float* out = (float*)d_out;

    init_state<<<128, 256>>>();
    embed_kernel<<<(LP1 * BB * DUNITS + 255) / 256, 256>>>(embedw, ys);

    {   // pre_enc[b][t][a] = tanh(hs[b,t,:] . Wenc[a,:] + benc[a])
        dim3 g(ATT_DIM / SG_BN, TT / SG_BM, BB);
        sgemm_tn<<<g, 256>>>(hs, Wenc, 0, TT, ATT_DIM, EPROJS,
                             (long)TT * EPROJS, (long)TT * ATT_DIM, benc, 1);
    }

    int cur = 0;
    for (int l = 0; l < LP1; l++) {
        dec_kernel<<<128, 256>>>(Wdec, cur);
        escore_kernel<<<128, 256>>>(hlens);
        ctx_kernel<<<128, 256>>>(hs, l);
        lstm_kernel<<<128, 256>>>(Wih0, Whh0, bih0, bhh0, 0, cur, l);
        lstm_kernel<<<128, 256>>>(Wih1, Whh1, bih1, bhh1, 1, cur, l);
        cur ^= 1;
    }

    {   // logits = zs @ Wout^T + bout
        dim3 g((ODIM + SG_BN - 1) / SG_BN, (NTOK + SG_BM - 1) / SG_BM, 1);
        sgemm_tn<<<g, 256>>>(nullptr, Wout, 1, NTOK, ODIM, DUNITS, 0L, 0L, bout, 0);
    }
    rowred_kernel<<<NTOK, 256>>>(ys);
    final_kernel<<<1, 256>>>(out);
    (void)in_sizes; (void)n_in; (void)out_size;
}